// round 4
// baseline (speedup 1.0000x reference)
#include <cuda_runtime.h>

#define DIM   768
#define HS    64
#define NSEQ  4096
#define BATCH 4
#define MROWS (BATCH * NSEQ)

typedef unsigned long long u64;

__device__ float g_q[MROWS * HS];
__device__ float g_k[MROWS * HS];
__device__ float g_v[MROWS * HS];

__device__ __forceinline__ u64 pack2(float lo, float hi) {
    u64 r; asm("mov.b64 %0, {%1, %2};" : "=l"(r) : "f"(lo), "f"(hi)); return r;
}
__device__ __forceinline__ u64 dup2(float x) {
    u64 r; asm("mov.b64 %0, {%1, %1};" : "=l"(r) : "f"(x)); return r;
}
__device__ __forceinline__ void unpack2(u64 v, float& lo, float& hi) {
    asm("mov.b64 {%0, %1}, %2;" : "=f"(lo), "=f"(hi) : "l"(v));
}
__device__ __forceinline__ u64 fma2(u64 a, u64 b, u64 c) {
    u64 d; asm("fma.rn.f32x2 %0, %1, %2, %3;" : "=l"(d) : "l"(a), "l"(b), "l"(c)); return d;
}
__device__ __forceinline__ u64 mul2(u64 a, u64 b) {
    u64 d; asm("mul.rn.f32x2 %0, %1, %2;" : "=l"(d) : "l"(a), "l"(b)); return d;
}

// ---------- Kernel 1: QKV projection, f32x2, A transposed in SMEM ----------
#define PBM 64
#define PBK 32
#define SAT 68

__global__ __launch_bounds__(256) void proj_kernel(
    const float* __restrict__ ix, const float* __restrict__ Wk,
    const float* __restrict__ Wq, const float* __restrict__ Wv)
{
    __shared__ float sAT[PBK * SAT];
    __shared__ float sB[PBK * HS];

    const float* W; float* outp;
    if (blockIdx.y == 0)      { W = Wq; outp = g_q; }
    else if (blockIdx.y == 1) { W = Wk; outp = g_k; }
    else                      { W = Wv; outp = g_v; }

    const int m0 = blockIdx.x * PBM, tid = threadIdx.x;
    const int ty = tid >> 4, tx = tid & 15;
    u64 acc[2][4] = {};

    for (int k0 = 0; k0 < DIM; k0 += PBK) {
        #pragma unroll
        for (int f = tid; f < PBM * PBK / 4; f += 256) {
            int row = f >> 3, kg = f & 7;
            float4 a = *(const float4*)(ix + (size_t)(m0 + row) * DIM + k0 + kg * 4);
            sAT[(4 * kg + 0) * SAT + row] = a.x;
            sAT[(4 * kg + 1) * SAT + row] = a.y;
            sAT[(4 * kg + 2) * SAT + row] = a.z;
            sAT[(4 * kg + 3) * SAT + row] = a.w;
        }
        #pragma unroll
        for (int f = tid; f < PBK * HS / 4; f += 256) {
            int row = f >> 4, hg = f & 15;
            *(float4*)&sB[row * HS + hg * 4] =
                *(const float4*)(W + (size_t)(k0 + row) * HS + hg * 4);
        }
        __syncthreads();
        #pragma unroll
        for (int k = 0; k < PBK; ++k) {
            ulonglong2 a = *(const ulonglong2*)&sAT[k * SAT + ty * 4];
            float4 b = *(const float4*)&sB[k * HS + tx * 4];
            u64 b0 = dup2(b.x), b1 = dup2(b.y), b2 = dup2(b.z), b3 = dup2(b.w);
            acc[0][0] = fma2(a.x, b0, acc[0][0]); acc[0][1] = fma2(a.x, b1, acc[0][1]);
            acc[0][2] = fma2(a.x, b2, acc[0][2]); acc[0][3] = fma2(a.x, b3, acc[0][3]);
            acc[1][0] = fma2(a.y, b0, acc[1][0]); acc[1][1] = fma2(a.y, b1, acc[1][1]);
            acc[1][2] = fma2(a.y, b2, acc[1][2]); acc[1][3] = fma2(a.y, b3, acc[1][3]);
        }
        __syncthreads();
    }
    #pragma unroll
    for (int i2 = 0; i2 < 2; ++i2) {
        float lo[4], hi[4];
        #pragma unroll
        for (int c = 0; c < 4; ++c) unpack2(acc[i2][c], lo[c], hi[c]);
        *(float4*)(outp + (size_t)(m0 + ty * 4 + 2 * i2) * HS + tx * 4) =
            make_float4(lo[0], lo[1], lo[2], lo[3]);
        *(float4*)(outp + (size_t)(m0 + ty * 4 + 2 * i2 + 1) * HS + tx * 4) =
            make_float4(hi[0], hi[1], hi[2], hi[3]);
    }
}

// ---------- Kernel 2: flash attention, FBM=32, 4 CTAs/SM ----------
#define FBM 32
#define FBN 64
#define SQT 36   // [64 h][36 rows]
#define SKV 68   // [64 key][68 h]
#define SPT 34   // [64 key][34 rows]

__global__ __launch_bounds__(128, 4) void flash_kernel(float* __restrict__ outp)
{
    extern __shared__ float sm[];
    float* sQT = sm;               // [64][36]
    float* sK  = sQT + HS * SQT;   // [64][68]
    float* sV  = sK + FBN * SKV;   // [64][68]
    float* sPT = sV + FBN * SKV;   // [64][34]

    const int bx = blockIdx.x, b = bx >> 7, qt = bx & 127;
    const float* Qg = g_q + ((size_t)b * NSEQ + qt * FBM) * HS;
    const float* Kg = g_k + (size_t)b * NSEQ * HS;
    const float* Vg = g_v + (size_t)b * NSEQ * HS;

    const int tid = threadIdx.x;
    const int ty = tid >> 4, tx = tid & 15;
    const int cg = tx & 7, jh = tx >> 3;

    // Load Q^T pre-scaled: rows ty*4..+3 per ty group, 32 rows total.
    for (int f = tid; f < FBM * HS / 4; f += 128) {
        int r = f >> 4, hg = f & 15;
        float4 q = *(const float4*)(Qg + (size_t)r * HS + hg * 4);
        sQT[(4 * hg + 0) * SQT + r] = q.x * 0.125f;
        sQT[(4 * hg + 1) * SQT + r] = q.y * 0.125f;
        sQT[(4 * hg + 2) * SQT + r] = q.z * 0.125f;
        sQT[(4 * hg + 3) * SQT + r] = q.w * 0.125f;
    }

    float m_i[4], l_i[4];
    #pragma unroll
    for (int i = 0; i < 4; ++i) { m_i[i] = -1e30f; l_i[i] = 0.0f; }
    u64 o2[2][8] = {};   // rows (4ty+2i2, +1), h cols cg*8..+7, keys j≡jh (mod 2)

    for (int kt = 0; kt < NSEQ / FBN; ++kt) {
        __syncthreads();
        const float* Kt = Kg + (size_t)kt * FBN * HS;
        const float* Vt = Vg + (size_t)kt * FBN * HS;
        #pragma unroll
        for (int f = tid; f < FBN * HS / 4; f += 128) {
            int row = f >> 4, hg = f & 15;
            *(float4*)&sK[row * SKV + hg * 4] = *(const float4*)(Kt + (size_t)row * HS + hg * 4);
            *(float4*)&sV[row * SKV + hg * 4] = *(const float4*)(Vt + (size_t)row * HS + hg * 4);
        }
        __syncthreads();

        // S = Q K^T : rows ty*4..+3 (2 pairs), cols tx+16*jj
        u64 s2[2][4] = {};
        #pragma unroll
        for (int h = 0; h < HS; h += 2) {
            ulonglong2 qa = *(const ulonglong2*)&sQT[h * SQT + ty * 4];
            ulonglong2 qb = *(const ulonglong2*)&sQT[(h + 1) * SQT + ty * 4];
            #pragma unroll
            for (int jj = 0; jj < 4; ++jj) {
                u64 kk = *(const u64*)&sK[(tx + 16 * jj) * SKV + h];
                float k0, k1; unpack2(kk, k0, k1);
                u64 kd0 = dup2(k0), kd1 = dup2(k1);
                s2[0][jj] = fma2(qa.x, kd0, s2[0][jj]);
                s2[0][jj] = fma2(qb.x, kd1, s2[0][jj]);
                s2[1][jj] = fma2(qa.y, kd0, s2[1][jj]);
                s2[1][jj] = fma2(qb.y, kd1, s2[1][jj]);
            }
        }

        // online softmax (rows shared by 16 tx lanes of a ty group)
        #pragma unroll
        for (int i2 = 0; i2 < 2; ++i2) {
            float a[4], bb[4];
            #pragma unroll
            for (int jj = 0; jj < 4; ++jj) unpack2(s2[i2][jj], a[jj], bb[jj]);
            float mxa = fmaxf(fmaxf(a[0], a[1]), fmaxf(a[2], a[3]));
            float mxb = fmaxf(fmaxf(bb[0], bb[1]), fmaxf(bb[2], bb[3]));
            #pragma unroll
            for (int o = 8; o >= 1; o >>= 1) {
                mxa = fmaxf(mxa, __shfl_xor_sync(0xffffffffu, mxa, o));
                mxb = fmaxf(mxb, __shfl_xor_sync(0xffffffffu, mxb, o));
            }
            const int ra = 2 * i2, rb = 2 * i2 + 1;
            float mna = fmaxf(m_i[ra], mxa), mnb = fmaxf(m_i[rb], mxb);
            float ala = __expf(m_i[ra] - mna), alb = __expf(m_i[rb] - mnb);
            float sa = 0.0f, sb = 0.0f;
            #pragma unroll
            for (int jj = 0; jj < 4; ++jj) {
                a[jj]  = __expf(a[jj]  - mna); sa += a[jj];
                bb[jj] = __expf(bb[jj] - mnb); sb += bb[jj];
            }
            #pragma unroll
            for (int o = 8; o >= 1; o >>= 1) {
                sa += __shfl_xor_sync(0xffffffffu, sa, o);
                sb += __shfl_xor_sync(0xffffffffu, sb, o);
            }
            l_i[ra] = l_i[ra] * ala + sa; m_i[ra] = mna;
            l_i[rb] = l_i[rb] * alb + sb; m_i[rb] = mnb;
            u64 al2 = pack2(ala, alb);
            #pragma unroll
            for (int c8 = 0; c8 < 8; ++c8) o2[i2][c8] = mul2(o2[i2][c8], al2);
            #pragma unroll
            for (int jj = 0; jj < 4; ++jj)
                *(u64*)&sPT[(tx + 16 * jj) * SPT + ty * 4 + 2 * i2] = pack2(a[jj], bb[jj]);
        }
        __syncthreads();

        // O += P V : keys j ≡ jh (mod 2), h cols cg*8..+7
        #pragma unroll 4
        for (int jj = 0; jj < FBN / 2; ++jj) {
            int j = jj * 2 + jh;
            u64 p0 = *(const u64*)&sPT[j * SPT + ty * 4];
            u64 p1 = *(const u64*)&sPT[j * SPT + ty * 4 + 2];
            ulonglong2 v01 = *(const ulonglong2*)&sV[j * SKV + cg * 8];
            ulonglong2 v23 = *(const ulonglong2*)&sV[j * SKV + cg * 8 + 4];
            float v[8];
            unpack2(v01.x, v[0], v[1]); unpack2(v01.y, v[2], v[3]);
            unpack2(v23.x, v[4], v[5]); unpack2(v23.y, v[6], v[7]);
            #pragma unroll
            for (int c8 = 0; c8 < 8; ++c8) {
                u64 vd = dup2(v[c8]);
                o2[0][c8] = fma2(p0, vd, o2[0][c8]);
                o2[1][c8] = fma2(p1, vd, o2[1][c8]);
            }
        }
    }

    // merge jh halves via SMEM, normalize, write
    __syncthreads();
    float* buf = sK;   // 64 slots x 32 floats = 8 KB, fits
    if (jh == 1) {
        int slot = (ty * 8 + cg) * 32;
        #pragma unroll
        for (int i2 = 0; i2 < 2; ++i2)
            #pragma unroll
            for (int c8 = 0; c8 < 8; ++c8)
                *(u64*)&buf[slot + (i2 * 8 + c8) * 2] = o2[i2][c8];
    }
    __syncthreads();
    if (jh == 0) {
        int slot = (ty * 8 + cg) * 32;
        float* Og = outp + ((size_t)b * NSEQ + qt * FBM) * HS;
        #pragma unroll
        for (int i2 = 0; i2 < 2; ++i2) {
            float il0 = 1.0f / l_i[2 * i2], il1 = 1.0f / l_i[2 * i2 + 1];
            float rlo[8], rhi[8];
            #pragma unroll
            for (int c8 = 0; c8 < 8; ++c8) {
                float x, y, p, q;
                unpack2(o2[i2][c8], x, y);
                unpack2(*(const u64*)&buf[slot + (i2 * 8 + c8) * 2], p, q);
                rlo[c8] = (x + p) * il0;
                rhi[c8] = (y + q) * il1;
            }
            int r0 = ty * 4 + 2 * i2;
            *(float4*)(Og + (size_t)r0 * HS + cg * 8)           = make_float4(rlo[0], rlo[1], rlo[2], rlo[3]);
            *(float4*)(Og + (size_t)r0 * HS + cg * 8 + 4)       = make_float4(rlo[4], rlo[5], rlo[6], rlo[7]);
            *(float4*)(Og + (size_t)(r0 + 1) * HS + cg * 8)     = make_float4(rhi[0], rhi[1], rhi[2], rhi[3]);
            *(float4*)(Og + (size_t)(r0 + 1) * HS + cg * 8 + 4) = make_float4(rhi[4], rhi[5], rhi[6], rhi[7]);
        }
    }
}

extern "C" void kernel_launch(void* const* d_in, const int* in_sizes, int n_in,
                              void* d_out, int out_size)
{
    (void)in_sizes; (void)n_in; (void)out_size;
    const float* ix = (const float*)d_in[0];
    const float* Wk = (const float*)d_in[1];
    const float* Wq = (const float*)d_in[2];
    const float* Wv = (const float*)d_in[3];
    float* out = (float*)d_out;

    const int smem_bytes = (HS * SQT + 2 * FBN * SKV + FBN * SPT) * (int)sizeof(float); // 52736
    cudaFuncSetAttribute(flash_kernel,
                         cudaFuncAttributeMaxDynamicSharedMemorySize, smem_bytes);

    dim3 pgrid(MROWS / PBM, 3);
    proj_kernel<<<pgrid, 256>>>(ix, Wk, Wq, Wv);
    flash_kernel<<<BATCH * (NSEQ / FBM), 128, smem_bytes>>>(out);
}

// round 5
// speedup vs baseline: 1.2878x; 1.2878x over previous
#include <cuda_runtime.h>

#define DIM   768
#define HS    64
#define NSEQ  4096
#define BATCH 4
#define MROWS (BATCH * NSEQ)

typedef unsigned long long u64;

__device__ float g_q[MROWS * HS];
__device__ float g_k[MROWS * HS];
__device__ float g_v[MROWS * HS];
__device__ float g_part0[MROWS * HS];
__device__ float g_part1[MROWS * HS];
__device__ float g_m0[MROWS], g_l0[MROWS], g_m1[MROWS], g_l1[MROWS];

__device__ __forceinline__ u64 pack2(float lo, float hi) {
    u64 r; asm("mov.b64 %0, {%1, %2};" : "=l"(r) : "f"(lo), "f"(hi)); return r;
}
__device__ __forceinline__ u64 dup2(float x) {
    u64 r; asm("mov.b64 %0, {%1, %1};" : "=l"(r) : "f"(x)); return r;
}
__device__ __forceinline__ void unpack2(u64 v, float& lo, float& hi) {
    asm("mov.b64 {%0, %1}, %2;" : "=f"(lo), "=f"(hi) : "l"(v));
}
__device__ __forceinline__ u64 fma2(u64 a, u64 b, u64 c) {
    u64 d; asm("fma.rn.f32x2 %0, %1, %2, %3;" : "=l"(d) : "l"(a), "l"(b), "l"(c)); return d;
}
__device__ __forceinline__ u64 mul2(u64 a, u64 b) {
    u64 d; asm("mul.rn.f32x2 %0, %1, %2;" : "=l"(d) : "l"(a), "l"(b)); return d;
}

// ---------- Kernel 1: QKV projection, 8x8 register tiles, 2 B/fma2 ----------
#define PBM 128
#define PBK 32
#define SAT 132

__global__ __launch_bounds__(128) void proj_kernel(
    const float* __restrict__ ix, const float* __restrict__ Wk,
    const float* __restrict__ Wq, const float* __restrict__ Wv)
{
    __shared__ float sAT[PBK * SAT];   // [k][row]  16.9 KB
    __shared__ float sB[PBK * HS];     // 8 KB

    const float* W; float* outp;
    if (blockIdx.y == 0)      { W = Wq; outp = g_q; }
    else if (blockIdx.y == 1) { W = Wk; outp = g_k; }
    else                      { W = Wv; outp = g_v; }

    const int m0 = blockIdx.x * PBM, tid = threadIdx.x;
    const int ty = tid >> 3;   // 0..15, rows ty*8..+7
    const int tx = tid & 7;    // 0..7,  cols tx*8..+7
    u64 acc[4][8] = {};

    for (int k0 = 0; k0 < DIM; k0 += PBK) {
        #pragma unroll
        for (int f = tid; f < PBM * PBK / 4; f += 128) {
            int row = f >> 3, kg = f & 7;
            float4 a = *(const float4*)(ix + (size_t)(m0 + row) * DIM + k0 + kg * 4);
            sAT[(4 * kg + 0) * SAT + row] = a.x;
            sAT[(4 * kg + 1) * SAT + row] = a.y;
            sAT[(4 * kg + 2) * SAT + row] = a.z;
            sAT[(4 * kg + 3) * SAT + row] = a.w;
        }
        #pragma unroll
        for (int f = tid; f < PBK * HS / 4; f += 128) {
            int row = f >> 4, hg = f & 15;
            *(float4*)&sB[row * HS + hg * 4] =
                *(const float4*)(W + (size_t)(k0 + row) * HS + hg * 4);
        }
        __syncthreads();
        #pragma unroll
        for (int k = 0; k < PBK; ++k) {
            ulonglong2 a0 = *(const ulonglong2*)&sAT[k * SAT + ty * 8];
            ulonglong2 a1 = *(const ulonglong2*)&sAT[k * SAT + ty * 8 + 4];
            float4 b0 = *(const float4*)&sB[k * HS + tx * 8];
            float4 b1 = *(const float4*)&sB[k * HS + tx * 8 + 4];
            u64 A[4] = {a0.x, a0.y, a1.x, a1.y};
            float bv[8] = {b0.x, b0.y, b0.z, b0.w, b1.x, b1.y, b1.z, b1.w};
            #pragma unroll
            for (int c = 0; c < 8; ++c) {
                u64 bd = dup2(bv[c]);
                #pragma unroll
                for (int rp = 0; rp < 4; ++rp)
                    acc[rp][c] = fma2(A[rp], bd, acc[rp][c]);
            }
        }
        __syncthreads();
    }
    #pragma unroll
    for (int rp = 0; rp < 4; ++rp) {
        float lo[8], hi[8];
        #pragma unroll
        for (int c = 0; c < 8; ++c) unpack2(acc[rp][c], lo[c], hi[c]);
        float* o0 = outp + (size_t)(m0 + ty * 8 + 2 * rp) * HS + tx * 8;
        float* o1 = o0 + HS;
        *(float4*)o0       = make_float4(lo[0], lo[1], lo[2], lo[3]);
        *(float4*)(o0 + 4) = make_float4(lo[4], lo[5], lo[6], lo[7]);
        *(float4*)o1       = make_float4(hi[0], hi[1], hi[2], hi[3]);
        *(float4*)(o1 + 4) = make_float4(hi[4], hi[5], hi[6], hi[7]);
    }
}

// ---------- Kernel 2: flash attention, FBM=64, split-K over 2 halves ----------
#define FBM 64
#define FBN 64
#define KSPLIT (NSEQ / 2)
#define SQT 68
#define SKV 68
#define SPT 66

__global__ __launch_bounds__(128, 3) void flash_kernel()
{
    extern __shared__ float sm[];
    float* sQT = sm;               // [64 h][68 row]
    float* sK  = sQT + HS * SQT;   // [64 key][68 h]
    float* sV  = sK + FBN * SKV;
    float* sPT = sV + FBN * SKV;   // [64 key][66 row] packed pairs

    const int bx = blockIdx.x, b = bx >> 6, qt = bx & 63;
    const int split = blockIdx.y;
    const float* Qg = g_q + ((size_t)b * NSEQ + qt * FBM) * HS;
    const float* Kg = g_k + ((size_t)b * NSEQ + split * KSPLIT) * HS;
    const float* Vg = g_v + ((size_t)b * NSEQ + split * KSPLIT) * HS;

    const int tid = threadIdx.x;
    const int ty = tid >> 4, tx = tid & 15;
    const int cg = tid & 7, jh = (tid >> 3) & 1;

    for (int f = tid; f < FBM * HS / 4; f += 128) {
        int r = f >> 4, hg = f & 15;
        float4 q = *(const float4*)(Qg + (size_t)r * HS + hg * 4);
        sQT[(4 * hg + 0) * SQT + r] = q.x * 0.125f;
        sQT[(4 * hg + 1) * SQT + r] = q.y * 0.125f;
        sQT[(4 * hg + 2) * SQT + r] = q.z * 0.125f;
        sQT[(4 * hg + 3) * SQT + r] = q.w * 0.125f;
    }

    float m_i[8], l_i[8];
    #pragma unroll
    for (int i = 0; i < 8; ++i) { m_i[i] = -1e30f; l_i[i] = 0.0f; }
    u64 o2[4][8] = {};

    for (int kt = 0; kt < KSPLIT / FBN; ++kt) {
        __syncthreads();
        const float* Kt = Kg + (size_t)kt * FBN * HS;
        const float* Vt = Vg + (size_t)kt * FBN * HS;
        #pragma unroll
        for (int f = tid; f < FBN * HS / 4; f += 128) {
            int row = f >> 4, hg = f & 15;
            *(float4*)&sK[row * SKV + hg * 4] = *(const float4*)(Kt + (size_t)row * HS + hg * 4);
            *(float4*)&sV[row * SKV + hg * 4] = *(const float4*)(Vt + (size_t)row * HS + hg * 4);
        }
        __syncthreads();

        u64 s2[4][4] = {};
        #pragma unroll
        for (int h = 0; h < HS; h += 2) {
            ulonglong2 qa0 = *(const ulonglong2*)&sQT[h * SQT + ty * 8];
            ulonglong2 qa1 = *(const ulonglong2*)&sQT[h * SQT + ty * 8 + 4];
            ulonglong2 qb0 = *(const ulonglong2*)&sQT[(h + 1) * SQT + ty * 8];
            ulonglong2 qb1 = *(const ulonglong2*)&sQT[(h + 1) * SQT + ty * 8 + 4];
            u64 qA[4] = {qa0.x, qa0.y, qa1.x, qa1.y};
            u64 qB[4] = {qb0.x, qb0.y, qb1.x, qb1.y};
            #pragma unroll
            for (int jj = 0; jj < 4; ++jj) {
                u64 kk = *(const u64*)&sK[(tx + 16 * jj) * SKV + h];
                float k0, k1; unpack2(kk, k0, k1);
                u64 kd0 = dup2(k0), kd1 = dup2(k1);
                #pragma unroll
                for (int i2 = 0; i2 < 4; ++i2) {
                    s2[i2][jj] = fma2(qA[i2], kd0, s2[i2][jj]);
                    s2[i2][jj] = fma2(qB[i2], kd1, s2[i2][jj]);
                }
            }
        }

        #pragma unroll
        for (int i2 = 0; i2 < 4; ++i2) {
            float a[4], bb[4];
            #pragma unroll
            for (int jj = 0; jj < 4; ++jj) unpack2(s2[i2][jj], a[jj], bb[jj]);
            float mxa = fmaxf(fmaxf(a[0], a[1]), fmaxf(a[2], a[3]));
            float mxb = fmaxf(fmaxf(bb[0], bb[1]), fmaxf(bb[2], bb[3]));
            #pragma unroll
            for (int o = 8; o >= 1; o >>= 1) {
                mxa = fmaxf(mxa, __shfl_xor_sync(0xffffffffu, mxa, o));
                mxb = fmaxf(mxb, __shfl_xor_sync(0xffffffffu, mxb, o));
            }
            const int ra = 2 * i2, rb = 2 * i2 + 1;
            float mna = fmaxf(m_i[ra], mxa), mnb = fmaxf(m_i[rb], mxb);
            float ala = __expf(m_i[ra] - mna), alb = __expf(m_i[rb] - mnb);
            float sa = 0.0f, sb = 0.0f;
            #pragma unroll
            for (int jj = 0; jj < 4; ++jj) {
                a[jj]  = __expf(a[jj]  - mna); sa += a[jj];
                bb[jj] = __expf(bb[jj] - mnb); sb += bb[jj];
            }
            #pragma unroll
            for (int o = 8; o >= 1; o >>= 1) {
                sa += __shfl_xor_sync(0xffffffffu, sa, o);
                sb += __shfl_xor_sync(0xffffffffu, sb, o);
            }
            l_i[ra] = l_i[ra] * ala + sa; m_i[ra] = mna;
            l_i[rb] = l_i[rb] * alb + sb; m_i[rb] = mnb;
            u64 al2 = pack2(ala, alb);
            #pragma unroll
            for (int c8 = 0; c8 < 8; ++c8) o2[i2][c8] = mul2(o2[i2][c8], al2);
            #pragma unroll
            for (int jj = 0; jj < 4; ++jj)
                *(u64*)&sPT[(tx + 16 * jj) * SPT + ty * 8 + 2 * i2] = pack2(a[jj], bb[jj]);
        }
        __syncthreads();

        #pragma unroll 2
        for (int jj = 0; jj < FBN / 2; ++jj) {
            int j = jj * 2 + jh;
            u64 p2[4];
            #pragma unroll
            for (int i2 = 0; i2 < 4; ++i2)
                p2[i2] = *(const u64*)&sPT[j * SPT + ty * 8 + 2 * i2];
            ulonglong2 v01 = *(const ulonglong2*)&sV[j * SKV + cg * 8];
            ulonglong2 v23 = *(const ulonglong2*)&sV[j * SKV + cg * 8 + 4];
            float v[8];
            unpack2(v01.x, v[0], v[1]); unpack2(v01.y, v[2], v[3]);
            unpack2(v23.x, v[4], v[5]); unpack2(v23.y, v[6], v[7]);
            #pragma unroll
            for (int c8 = 0; c8 < 8; ++c8) {
                u64 vd = dup2(v[c8]);
                #pragma unroll
                for (int i2 = 0; i2 < 4; ++i2)
                    o2[i2][c8] = fma2(p2[i2], vd, o2[i2][c8]);
            }
        }
    }

    // merge jh halves via SMEM; write UNNORMALIZED partial + stats
    __syncthreads();
    float* buf = sK;
    if (jh == 1) {
        int slot = (ty * 8 + cg) * 64;
        #pragma unroll
        for (int i2 = 0; i2 < 4; ++i2)
            #pragma unroll
            for (int c8 = 0; c8 < 8; ++c8)
                *(u64*)&buf[slot + (i2 * 8 + c8) * 2] = o2[i2][c8];
    }
    __syncthreads();

    const int rowbase = b * NSEQ + qt * FBM;
    float* Mp = split ? g_m1 : g_m0;
    float* Lp = split ? g_l1 : g_l0;
    float* Pp = split ? g_part1 : g_part0;

    if (tx == 0) {
        #pragma unroll
        for (int i = 0; i < 8; ++i) {
            Mp[rowbase + ty * 8 + i] = m_i[i];
            Lp[rowbase + ty * 8 + i] = l_i[i];
        }
    }
    if (jh == 0) {
        int slot = (ty * 8 + cg) * 64;
        float* Og = Pp + (size_t)rowbase * HS;
        #pragma unroll
        for (int i2 = 0; i2 < 4; ++i2) {
            float rlo[8], rhi[8];
            #pragma unroll
            for (int c8 = 0; c8 < 8; ++c8) {
                float x, y, p, q;
                unpack2(o2[i2][c8], x, y);
                unpack2(*(const u64*)&buf[slot + (i2 * 8 + c8) * 2], p, q);
                rlo[c8] = x + p;
                rhi[c8] = y + q;
            }
            int r0 = ty * 8 + 2 * i2;
            *(float4*)(Og + (size_t)r0 * HS + cg * 8)           = make_float4(rlo[0], rlo[1], rlo[2], rlo[3]);
            *(float4*)(Og + (size_t)r0 * HS + cg * 8 + 4)       = make_float4(rlo[4], rlo[5], rlo[6], rlo[7]);
            *(float4*)(Og + (size_t)(r0 + 1) * HS + cg * 8)     = make_float4(rhi[0], rhi[1], rhi[2], rhi[3]);
            *(float4*)(Og + (size_t)(r0 + 1) * HS + cg * 8 + 4) = make_float4(rhi[4], rhi[5], rhi[6], rhi[7]);
        }
    }
}

// ---------- Kernel 3: merge the two splits ----------
__global__ __launch_bounds__(128) void merge_kernel(float* __restrict__ out)
{
    const int r  = blockIdx.x * 64 + (threadIdx.x >> 1);
    const int h0 = (threadIdx.x & 1) * 32;
    float m0 = g_m0[r], m1 = g_m1[r];
    float m  = fmaxf(m0, m1);
    float w0 = __expf(m0 - m), w1 = __expf(m1 - m);
    float inv = 1.0f / (g_l0[r] * w0 + g_l1[r] * w1);
    const float4* p0 = (const float4*)(g_part0 + (size_t)r * HS + h0);
    const float4* p1 = (const float4*)(g_part1 + (size_t)r * HS + h0);
    float4* po = (float4*)(out + (size_t)r * HS + h0);
    #pragma unroll
    for (int i = 0; i < 8; ++i) {
        float4 a = p0[i], bq = p1[i];
        po[i] = make_float4((a.x * w0 + bq.x * w1) * inv,
                            (a.y * w0 + bq.y * w1) * inv,
                            (a.z * w0 + bq.z * w1) * inv,
                            (a.w * w0 + bq.w * w1) * inv);
    }
}

extern "C" void kernel_launch(void* const* d_in, const int* in_sizes, int n_in,
                              void* d_out, int out_size)
{
    (void)in_sizes; (void)n_in; (void)out_size;
    const float* ix = (const float*)d_in[0];
    const float* Wk = (const float*)d_in[1];
    const float* Wq = (const float*)d_in[2];
    const float* Wv = (const float*)d_in[3];
    float* out = (float*)d_out;

    const int smem_bytes = (HS * SQT + 2 * FBN * SKV + FBN * SPT) * (int)sizeof(float);
    cudaFuncSetAttribute(flash_kernel,
                         cudaFuncAttributeMaxDynamicSharedMemorySize, smem_bytes);

    dim3 pgrid(MROWS / PBM, 3);                 // (128, 3)
    proj_kernel<<<pgrid, 128>>>(ix, Wk, Wq, Wv);

    dim3 fgrid(BATCH * (NSEQ / FBM), 2);        // (256, 2) = 512 CTAs
    flash_kernel<<<fgrid, 128, smem_bytes>>>();

    merge_kernel<<<MROWS / 64, 128>>>(out);     // 256 blocks
}

// round 7
// speedup vs baseline: 2.3505x; 1.8253x over previous
#include <cuda_runtime.h>
#include <cuda_bf16.h>
#include <cstdint>

#define DIM   768
#define HS    64
#define NSEQ  4096
#define BATCH 4
#define MROWS (BATCH * NSEQ)

typedef unsigned long long u64;
typedef uint32_t u32;

// bf16x2-packed staging (hi/lo split). 16 MB total, device globals.
__device__ u32 g_qh2[MROWS * 32], g_ql2[MROWS * 32];
__device__ u32 g_kh2[MROWS * 32], g_kl2[MROWS * 32];
__device__ u32 g_vh2[MROWS * 32], g_vl2[MROWS * 32];
__device__ u32 g_vth2[BATCH * HS * (NSEQ / 2)], g_vtl2[BATCH * HS * (NSEQ / 2)];

// ---- f32x2 helpers (proj) ----
__device__ __forceinline__ u64 dup2(float x) {
    u64 r; asm("mov.b64 %0, {%1, %1};" : "=l"(r) : "f"(x)); return r;
}
__device__ __forceinline__ void unpack2(u64 v, float& lo, float& hi) {
    asm("mov.b64 {%0, %1}, %2;" : "=f"(lo), "=f"(hi) : "l"(v));
}
__device__ __forceinline__ u64 fma2(u64 a, u64 b, u64 c) {
    u64 d; asm("fma.rn.f32x2 %0, %1, %2, %3;" : "=l"(d) : "l"(a), "l"(b), "l"(c)); return d;
}

// ---- bf16 helpers ----
__device__ __forceinline__ u32 packbf(float lo, float hi) {   // low half = lo
    u32 r; asm("cvt.rn.satfinite.bf16x2.f32 %0, %1, %2;" : "=r"(r) : "f"(hi), "f"(lo)); return r;
}
__device__ __forceinline__ float bf16r(float x) { return __bfloat162float(__float2bfloat16(x)); }

// ---- HMMA m16n8k16 bf16 (arch-generic, runs on tensor pipe) ----
__device__ __forceinline__ void mma16816(float4& d, const u32* a, u32 b0, u32 b1) {
    asm volatile("mma.sync.aligned.m16n8k16.row.col.f32.bf16.bf16.f32 "
        "{%0,%1,%2,%3}, {%4,%5,%6,%7}, {%8,%9}, {%0,%1,%2,%3};"
        : "+f"(d.x), "+f"(d.y), "+f"(d.z), "+f"(d.w)
        : "r"(a[0]), "r"(a[1]), "r"(a[2]), "r"(a[3]), "r"(b0), "r"(b1));
}

// ---------- Kernel 1: QKV projection -> bf16 hi/lo staging ----------
#define PBM 128
#define PBK 32
#define SAT 132

__global__ __launch_bounds__(128) void proj_kernel(
    const float* __restrict__ ix, const float* __restrict__ Wk,
    const float* __restrict__ Wq, const float* __restrict__ Wv)
{
    __shared__ float sAT[PBK * SAT];
    __shared__ float sB[PBK * HS];

    const float* W; u32 *oh, *ol; float scale;
    if (blockIdx.y == 0)      { W = Wq; oh = g_qh2; ol = g_ql2; scale = 0.125f; }
    else if (blockIdx.y == 1) { W = Wk; oh = g_kh2; ol = g_kl2; scale = 1.0f; }
    else                      { W = Wv; oh = g_vh2; ol = g_vl2; scale = 1.0f; }

    const int m0 = blockIdx.x * PBM, tid = threadIdx.x;
    const int ty = tid >> 3, tx = tid & 7;
    u64 acc[4][8] = {};

    for (int k0 = 0; k0 < DIM; k0 += PBK) {
        #pragma unroll
        for (int f = tid; f < PBM * PBK / 4; f += 128) {
            int row = f >> 3, kg = f & 7;
            float4 a = *(const float4*)(ix + (size_t)(m0 + row) * DIM + k0 + kg * 4);
            sAT[(4 * kg + 0) * SAT + row] = a.x;
            sAT[(4 * kg + 1) * SAT + row] = a.y;
            sAT[(4 * kg + 2) * SAT + row] = a.z;
            sAT[(4 * kg + 3) * SAT + row] = a.w;
        }
        #pragma unroll
        for (int f = tid; f < PBK * HS / 4; f += 128) {
            int row = f >> 4, hg = f & 15;
            *(float4*)&sB[row * HS + hg * 4] =
                *(const float4*)(W + (size_t)(k0 + row) * HS + hg * 4);
        }
        __syncthreads();
        #pragma unroll
        for (int k = 0; k < PBK; ++k) {
            ulonglong2 a0 = *(const ulonglong2*)&sAT[k * SAT + ty * 8];
            ulonglong2 a1 = *(const ulonglong2*)&sAT[k * SAT + ty * 8 + 4];
            float4 b0 = *(const float4*)&sB[k * HS + tx * 8];
            float4 b1 = *(const float4*)&sB[k * HS + tx * 8 + 4];
            u64 A[4] = {a0.x, a0.y, a1.x, a1.y};
            float bv[8] = {b0.x, b0.y, b0.z, b0.w, b1.x, b1.y, b1.z, b1.w};
            #pragma unroll
            for (int c = 0; c < 8; ++c) {
                u64 bd = dup2(bv[c]);
                #pragma unroll
                for (int rp = 0; rp < 4; ++rp)
                    acc[rp][c] = fma2(A[rp], bd, acc[rp][c]);
            }
        }
        __syncthreads();
    }
    #pragma unroll
    for (int rp = 0; rp < 4; ++rp) {
        float lo[8], hi[8];
        #pragma unroll
        for (int c = 0; c < 8; ++c) unpack2(acc[rp][c], lo[c], hi[c]);
        const int r0 = m0 + ty * 8 + 2 * rp, r1 = r0 + 1;
        u32 ph[4], pl[4], qh[4], ql[4];
        #pragma unroll
        for (int i = 0; i < 4; ++i) {
            float x0 = lo[2 * i] * scale, x1 = lo[2 * i + 1] * scale;
            float h0 = bf16r(x0), h1 = bf16r(x1);
            ph[i] = packbf(h0, h1); pl[i] = packbf(x0 - h0, x1 - h1);
            float y0 = hi[2 * i] * scale, y1 = hi[2 * i + 1] * scale;
            float g0 = bf16r(y0), g1 = bf16r(y1);
            qh[i] = packbf(g0, g1); ql[i] = packbf(y0 - g0, y1 - g1);
        }
        *(uint4*)&oh[(size_t)r0 * 32 + tx * 4] = make_uint4(ph[0], ph[1], ph[2], ph[3]);
        *(uint4*)&ol[(size_t)r0 * 32 + tx * 4] = make_uint4(pl[0], pl[1], pl[2], pl[3]);
        *(uint4*)&oh[(size_t)r1 * 32 + tx * 4] = make_uint4(qh[0], qh[1], qh[2], qh[3]);
        *(uint4*)&ol[(size_t)r1 * 32 + tx * 4] = make_uint4(ql[0], ql[1], ql[2], ql[3]);
    }
}

// ---------- Kernel 1b: V transpose -> [b][h][j] bf16 hi/lo ----------
__global__ __launch_bounds__(128) void vt_kernel()
{
    __shared__ unsigned short th[64 * 66], tl[64 * 66];
    const int jb = blockIdx.x, b = blockIdx.y;
    const int tid = threadIdx.x;

    #pragma unroll
    for (int f = tid; f < 64 * 32; f += 128) {
        int r = f >> 5, c = f & 31;
        size_t src = ((size_t)(b * NSEQ + jb * 64 + r)) * 32 + c;
        *(u32*)&th[r * 66 + 2 * c] = g_vh2[src];
        *(u32*)&tl[r * 66 + 2 * c] = g_vl2[src];
    }
    __syncthreads();

    const int h = tid >> 1, half = tid & 1;
    #pragma unroll
    for (int i = 0; i < 16; ++i) {
        int j0 = half * 32 + 2 * i;
        u32 vh = (u32)th[j0 * 66 + h] | ((u32)th[(j0 + 1) * 66 + h] << 16);
        u32 vl = (u32)tl[j0 * 66 + h] | ((u32)tl[(j0 + 1) * 66 + h] << 16);
        size_t dst = ((size_t)(b * HS + h)) * (NSEQ / 2) + jb * 32 + half * 16 + i;
        g_vth2[dst] = vh;
        g_vtl2[dst] = vl;
    }
}

// ---------- Kernel 2: HMMA flash attention ----------
// CTA = 64 q rows, 4 warps (16 rows each), key tiles of 128, grid 256.
#define KSTR 36   // u32 row stride for K tiles (72 bf16)
#define VSTR 68   // u32 row stride for Vt tiles (136 bf16)

__global__ __launch_bounds__(128) void flash_tc(float* __restrict__ outp)
{
    extern __shared__ __align__(16) u32 sm4[];
    u32* sKh = sm4;                    // [128][36]
    u32* sKl = sm4 + 128 * KSTR;
    u32* sVh = sm4 + 2 * 128 * KSTR;   // [64][68]
    u32* sVl = sVh + 64 * VSTR;

    const int tid = threadIdx.x, w = tid >> 5, lane = tid & 31;
    const int gid = lane >> 2, tig = lane & 3;
    const int b = blockIdx.x >> 6, qt = blockIdx.x & 63;

    // Q fragments (persistent): a0..a3 per k16-step s
    u32 Qh[4][4], Ql[4][4];
    {
        const u32* qh = g_qh2 + ((size_t)(b * NSEQ + qt * 64 + w * 16)) * 32;
        const u32* ql = g_ql2 + ((size_t)(b * NSEQ + qt * 64 + w * 16)) * 32;
        #pragma unroll
        for (int s = 0; s < 4; ++s) {
            Qh[s][0] = qh[(size_t)gid * 32 + 8 * s + tig];
            Qh[s][1] = qh[(size_t)(gid + 8) * 32 + 8 * s + tig];
            Qh[s][2] = qh[(size_t)gid * 32 + 8 * s + 4 + tig];
            Qh[s][3] = qh[(size_t)(gid + 8) * 32 + 8 * s + 4 + tig];
            Ql[s][0] = ql[(size_t)gid * 32 + 8 * s + tig];
            Ql[s][1] = ql[(size_t)(gid + 8) * 32 + 8 * s + tig];
            Ql[s][2] = ql[(size_t)gid * 32 + 8 * s + 4 + tig];
            Ql[s][3] = ql[(size_t)(gid + 8) * 32 + 8 * s + 4 + tig];
        }
    }

    float4 O[8];
    #pragma unroll
    for (int u = 0; u < 8; ++u) O[u] = make_float4(0.f, 0.f, 0.f, 0.f);
    float m0r = -1e30f, m1r = -1e30f, l0r = 0.f, l1r = 0.f;

    for (int kt = 0; kt < NSEQ / 128; ++kt) {
        __syncthreads();
        const uint4* Kh4 = (const uint4*)(g_kh2 + ((size_t)(b * NSEQ + kt * 128)) * 32);
        const uint4* Kl4 = (const uint4*)(g_kl2 + ((size_t)(b * NSEQ + kt * 128)) * 32);
        #pragma unroll
        for (int f = tid; f < 1024; f += 128) {
            int row = f >> 3, c = f & 7;
            *(uint4*)&sKh[row * KSTR + c * 4] = Kh4[row * 8 + c];
            *(uint4*)&sKl[row * KSTR + c * 4] = Kl4[row * 8 + c];
        }
        const uint4* Vh4 = (const uint4*)(g_vth2 + (size_t)b * HS * (NSEQ / 2));
        const uint4* Vl4 = (const uint4*)(g_vtl2 + (size_t)b * HS * (NSEQ / 2));
        #pragma unroll
        for (int f = tid; f < 1024; f += 128) {
            int h = f >> 4, c = f & 15;
            *(uint4*)&sVh[h * VSTR + c * 4] = Vh4[h * 512 + kt * 16 + c];
            *(uint4*)&sVl[h * VSTR + c * 4] = Vl4[h * 512 + kt * 16 + c];
        }
        __syncthreads();

        // ---- S = Q K^T : 16 n-steps x 4 k-steps x 3 terms ----
        float4 S[16];
        #pragma unroll
        for (int t = 0; t < 16; ++t) S[t] = make_float4(0.f, 0.f, 0.f, 0.f);
        #pragma unroll
        for (int t = 0; t < 16; ++t) {
            int base = (8 * t + gid) * KSTR;
            #pragma unroll
            for (int s = 0; s < 4; ++s) {
                u32 bh0 = sKh[base + 8 * s + tig],     bh1 = sKh[base + 8 * s + 4 + tig];
                u32 bl0 = sKl[base + 8 * s + tig],     bl1 = sKl[base + 8 * s + 4 + tig];
                mma16816(S[t], Qh[s], bh0, bh1);
                mma16816(S[t], Qh[s], bl0, bl1);
                mma16816(S[t], Ql[s], bh0, bh1);
            }
        }

        // ---- online softmax (rows gid, gid+8; quad covers all 128 cols) ----
        float nm0 = m0r, nm1 = m1r;
        #pragma unroll
        for (int t = 0; t < 16; ++t) {
            nm0 = fmaxf(nm0, fmaxf(S[t].x, S[t].y));
            nm1 = fmaxf(nm1, fmaxf(S[t].z, S[t].w));
        }
        nm0 = fmaxf(nm0, __shfl_xor_sync(0xffffffffu, nm0, 1));
        nm0 = fmaxf(nm0, __shfl_xor_sync(0xffffffffu, nm0, 2));
        nm1 = fmaxf(nm1, __shfl_xor_sync(0xffffffffu, nm1, 1));
        nm1 = fmaxf(nm1, __shfl_xor_sync(0xffffffffu, nm1, 2));
        float al0 = __expf(m0r - nm0), al1 = __expf(m1r - nm1);
        m0r = nm0; m1r = nm1;
        float s0 = 0.f, s1 = 0.f;
        #pragma unroll
        for (int t = 0; t < 16; ++t) {
            S[t].x = __expf(S[t].x - nm0); S[t].y = __expf(S[t].y - nm0);
            S[t].z = __expf(S[t].z - nm1); S[t].w = __expf(S[t].w - nm1);
            s0 += S[t].x + S[t].y; s1 += S[t].z + S[t].w;
        }
        s0 += __shfl_xor_sync(0xffffffffu, s0, 1);
        s0 += __shfl_xor_sync(0xffffffffu, s0, 2);
        s1 += __shfl_xor_sync(0xffffffffu, s1, 1);
        s1 += __shfl_xor_sync(0xffffffffu, s1, 2);
        l0r = l0r * al0 + s0; l1r = l1r * al1 + s1;
        #pragma unroll
        for (int u = 0; u < 8; ++u) {
            O[u].x *= al0; O[u].y *= al0; O[u].z *= al1; O[u].w *= al1;
        }

        // ---- O += P V : P fragments come straight from S registers ----
        #pragma unroll
        for (int s = 0; s < 8; ++s) {
            u32 ph[4], pl[4];
            ph[0] = packbf(S[2 * s].x,     S[2 * s].y);
            ph[1] = packbf(S[2 * s].z,     S[2 * s].w);
            ph[2] = packbf(S[2 * s + 1].x, S[2 * s + 1].y);
            ph[3] = packbf(S[2 * s + 1].z, S[2 * s + 1].w);
            pl[0] = packbf(S[2 * s].x     - __uint_as_float(ph[0] << 16),
                           S[2 * s].y     - __uint_as_float(ph[0] & 0xFFFF0000u));
            pl[1] = packbf(S[2 * s].z     - __uint_as_float(ph[1] << 16),
                           S[2 * s].w     - __uint_as_float(ph[1] & 0xFFFF0000u));
            pl[2] = packbf(S[2 * s + 1].x - __uint_as_float(ph[2] << 16),
                           S[2 * s + 1].y - __uint_as_float(ph[2] & 0xFFFF0000u));
            pl[3] = packbf(S[2 * s + 1].z - __uint_as_float(ph[3] << 16),
                           S[2 * s + 1].w - __uint_as_float(ph[3] & 0xFFFF0000u));
            #pragma unroll
            for (int u = 0; u < 8; ++u) {
                int base = (8 * u + gid) * VSTR + 8 * s + tig;
                u32 bh0 = sVh[base], bh1 = sVh[base + 4];
                u32 bl0 = sVl[base], bl1 = sVl[base + 4];
                mma16816(O[u], ph, bh0, bh1);
                mma16816(O[u], ph, bl0, bl1);
                mma16816(O[u], pl, bh0, bh1);
            }
        }
    }

    // ---- normalize + write ----
    float i0 = 1.f / l0r, i1 = 1.f / l1r;
    float* o0 = outp + ((size_t)(b * NSEQ + qt * 64 + w * 16 + gid)) * HS;
    float* o1 = o0 + 8 * HS;
    #pragma unroll
    for (int u = 0; u < 8; ++u) {
        *(float2*)(o0 + 8 * u + 2 * tig) = make_float2(O[u].x * i0, O[u].y * i0);
        *(float2*)(o1 + 8 * u + 2 * tig) = make_float2(O[u].z * i1, O[u].w * i1);
    }
}

// ---------------- Launch ----------------
extern "C" void kernel_launch(void* const* d_in, const int* in_sizes, int n_in,
                              void* d_out, int out_size)
{
    (void)in_sizes; (void)n_in; (void)out_size;
    const float* ix = (const float*)d_in[0];
    const float* Wk = (const float*)d_in[1];
    const float* Wq = (const float*)d_in[2];
    const float* Wv = (const float*)d_in[3];
    float* out = (float*)d_out;

    const int smem_bytes = (2 * 128 * KSTR + 2 * 64 * VSTR) * 4;  // 71680
    cudaFuncSetAttribute(flash_tc,
                         cudaFuncAttributeMaxDynamicSharedMemorySize, smem_bytes);

    dim3 pgrid(MROWS / PBM, 3);
    proj_kernel<<<pgrid, 128>>>(ix, Wk, Wq, Wv);

    dim3 vgrid(NSEQ / 64, BATCH);
    vt_kernel<<<vgrid, 128>>>();

    flash_tc<<<BATCH * (NSEQ / 64), 128, smem_bytes>>>(out);  // 256 CTAs
}

// round 8
// speedup vs baseline: 2.9016x; 1.2344x over previous
#include <cuda_runtime.h>
#include <cuda_bf16.h>
#include <cstdint>

#define DIM   768
#define HS    64
#define NSEQ  4096
#define BATCH 4
#define MROWS (BATCH * NSEQ)

typedef uint32_t u32;

// bf16x2-packed staging (hi/lo split), device globals.
__device__ u32 g_qh2[MROWS * 32], g_ql2[MROWS * 32];
__device__ u32 g_kh2[MROWS * 32], g_kl2[MROWS * 32];
__device__ u32 g_vh2[MROWS * 32], g_vl2[MROWS * 32];
__device__ u32 g_vth2[BATCH * HS * (NSEQ / 2)], g_vtl2[BATCH * HS * (NSEQ / 2)];

// ---- bf16 helpers ----
__device__ __forceinline__ u32 packbf(float lo, float hi) {   // low half = lo
    u32 r; asm("cvt.rn.satfinite.bf16x2.f32 %0, %1, %2;" : "=r"(r) : "f"(hi), "f"(lo)); return r;
}
__device__ __forceinline__ float bf16r(float x) { return __bfloat162float(__float2bfloat16(x)); }

// ---- HMMA m16n8k16 bf16 ----
__device__ __forceinline__ void mma16816(float4& d, const u32* a, u32 b0, u32 b1) {
    asm volatile("mma.sync.aligned.m16n8k16.row.col.f32.bf16.bf16.f32 "
        "{%0,%1,%2,%3}, {%4,%5,%6,%7}, {%8,%9}, {%0,%1,%2,%3};"
        : "+f"(d.x), "+f"(d.y), "+f"(d.z), "+f"(d.w)
        : "r"(a[0]), "r"(a[1]), "r"(a[2]), "r"(a[3]), "r"(b0), "r"(b1));
}

// ---------- Kernel 1: QKV projection via HMMA, bf16 hi/lo 3-term ----------
// CTA = 128 rows x 64 cols (one weight), K chunks of 32. 4 warps, 32 rows each.
#define PSTR 20   // u32 row stride: (20*gid+tig) mod 32 covers all banks

__global__ __launch_bounds__(128, 3) void proj_tc(
    const float* __restrict__ ix, const float* __restrict__ Wk,
    const float* __restrict__ Wq, const float* __restrict__ Wv)
{
    __shared__ u32 sAh[128 * PSTR], sAl[128 * PSTR];  // ix chunk hi/lo pairs
    __shared__ u32 sWh[64 * PSTR],  sWl[64 * PSTR];   // W^T chunk hi/lo pairs

    const float* W; u32 *oh, *ol; float scale;
    if (blockIdx.y == 0)      { W = Wq; oh = g_qh2; ol = g_ql2; scale = 0.125f; }
    else if (blockIdx.y == 1) { W = Wk; oh = g_kh2; ol = g_kl2; scale = 1.0f; }
    else                      { W = Wv; oh = g_vh2; ol = g_vl2; scale = 1.0f; }

    const int tid = threadIdx.x, w = tid >> 5, lane = tid & 31;
    const int gid = lane >> 2, tig = lane & 3;
    const int m0 = blockIdx.x * 128;

    float4 acc[2][8];
    #pragma unroll
    for (int mt = 0; mt < 2; ++mt)
        #pragma unroll
        for (int nt = 0; nt < 8; ++nt) acc[mt][nt] = make_float4(0.f, 0.f, 0.f, 0.f);

    for (int k0 = 0; k0 < DIM; k0 += 32) {
        __syncthreads();
        // A chunk: 128 rows x 16 pairs
        #pragma unroll
        for (int f = tid; f < 128 * 16; f += 128) {
            int row = f >> 4, pr = f & 15;
            float2 a = *(const float2*)(ix + (size_t)(m0 + row) * DIM + k0 + 2 * pr);
            float h0 = bf16r(a.x), h1 = bf16r(a.y);
            sAh[row * PSTR + pr] = packbf(h0, h1);
            sAl[row * PSTR + pr] = packbf(a.x - h0, a.y - h1);
        }
        // W^T chunk: 64 n-rows x 16 pairs
        {
            int n = tid & 63, kph = tid >> 6;
            #pragma unroll
            for (int kp = kph; kp < 16; kp += 2) {
                float w0 = W[(size_t)(k0 + 2 * kp) * HS + n];
                float w1 = W[(size_t)(k0 + 2 * kp + 1) * HS + n];
                float h0 = bf16r(w0), h1 = bf16r(w1);
                sWh[n * PSTR + kp] = packbf(h0, h1);
                sWl[n * PSTR + kp] = packbf(w0 - h0, w1 - h1);
            }
        }
        __syncthreads();

        #pragma unroll
        for (int s = 0; s < 2; ++s) {
            u32 Ah[2][4], Al[2][4];
            #pragma unroll
            for (int mt = 0; mt < 2; ++mt) {
                int r = w * 32 + mt * 16;
                Ah[mt][0] = sAh[(r + gid) * PSTR + 8 * s + tig];
                Ah[mt][1] = sAh[(r + gid + 8) * PSTR + 8 * s + tig];
                Ah[mt][2] = sAh[(r + gid) * PSTR + 8 * s + 4 + tig];
                Ah[mt][3] = sAh[(r + gid + 8) * PSTR + 8 * s + 4 + tig];
                Al[mt][0] = sAl[(r + gid) * PSTR + 8 * s + tig];
                Al[mt][1] = sAl[(r + gid + 8) * PSTR + 8 * s + tig];
                Al[mt][2] = sAl[(r + gid) * PSTR + 8 * s + 4 + tig];
                Al[mt][3] = sAl[(r + gid + 8) * PSTR + 8 * s + 4 + tig];
            }
            #pragma unroll
            for (int nt = 0; nt < 8; ++nt) {
                int nb = (8 * nt + gid) * PSTR + 8 * s;
                u32 bh0 = sWh[nb + tig], bh1 = sWh[nb + 4 + tig];
                u32 bl0 = sWl[nb + tig], bl1 = sWl[nb + 4 + tig];
                #pragma unroll
                for (int mt = 0; mt < 2; ++mt) {
                    mma16816(acc[mt][nt], Ah[mt], bh0, bh1);
                    mma16816(acc[mt][nt], Ah[mt], bl0, bl1);
                    mma16816(acc[mt][nt], Al[mt], bh0, bh1);
                }
            }
        }
    }

    // write staging hi/lo (scaled)
    #pragma unroll
    for (int mt = 0; mt < 2; ++mt) {
        int row0 = m0 + w * 32 + mt * 16 + gid;
        int row1 = row0 + 8;
        #pragma unroll
        for (int nt = 0; nt < 8; ++nt) {
            float4 d = acc[mt][nt];
            float x0 = d.x * scale, x1 = d.y * scale;
            float y0 = d.z * scale, y1 = d.w * scale;
            float hx0 = bf16r(x0), hx1 = bf16r(x1);
            float hy0 = bf16r(y0), hy1 = bf16r(y1);
            oh[(size_t)row0 * 32 + 4 * nt + tig] = packbf(hx0, hx1);
            ol[(size_t)row0 * 32 + 4 * nt + tig] = packbf(x0 - hx0, x1 - hx1);
            oh[(size_t)row1 * 32 + 4 * nt + tig] = packbf(hy0, hy1);
            ol[(size_t)row1 * 32 + 4 * nt + tig] = packbf(y0 - hy0, y1 - hy1);
        }
    }
}

// ---------- Kernel 1b: V transpose -> [b][h][j] bf16 hi/lo ----------
__global__ __launch_bounds__(128) void vt_kernel()
{
    __shared__ unsigned short th[64 * 66], tl[64 * 66];
    const int jb = blockIdx.x, b = blockIdx.y;
    const int tid = threadIdx.x;

    #pragma unroll
    for (int f = tid; f < 64 * 32; f += 128) {
        int r = f >> 5, c = f & 31;
        size_t src = ((size_t)(b * NSEQ + jb * 64 + r)) * 32 + c;
        *(u32*)&th[r * 66 + 2 * c] = g_vh2[src];
        *(u32*)&tl[r * 66 + 2 * c] = g_vl2[src];
    }
    __syncthreads();

    const int h = tid >> 1, half = tid & 1;
    #pragma unroll
    for (int i = 0; i < 16; ++i) {
        int j0 = half * 32 + 2 * i;
        u32 vh = (u32)th[j0 * 66 + h] | ((u32)th[(j0 + 1) * 66 + h] << 16);
        u32 vl = (u32)tl[j0 * 66 + h] | ((u32)tl[(j0 + 1) * 66 + h] << 16);
        size_t dst = ((size_t)(b * HS + h)) * (NSEQ / 2) + jb * 32 + half * 16 + i;
        g_vth2[dst] = vh;
        g_vtl2[dst] = vl;
    }
}

// ---------- Kernel 2: HMMA flash attention (unchanged from R7) ----------
#define KSTR 36
#define VSTR 68

__global__ __launch_bounds__(128) void flash_tc(float* __restrict__ outp)
{
    extern __shared__ __align__(16) u32 sm4[];
    u32* sKh = sm4;
    u32* sKl = sm4 + 128 * KSTR;
    u32* sVh = sm4 + 2 * 128 * KSTR;
    u32* sVl = sVh + 64 * VSTR;

    const int tid = threadIdx.x, w = tid >> 5, lane = tid & 31;
    const int gid = lane >> 2, tig = lane & 3;
    const int b = blockIdx.x >> 6, qt = blockIdx.x & 63;

    u32 Qh[4][4], Ql[4][4];
    {
        const u32* qh = g_qh2 + ((size_t)(b * NSEQ + qt * 64 + w * 16)) * 32;
        const u32* ql = g_ql2 + ((size_t)(b * NSEQ + qt * 64 + w * 16)) * 32;
        #pragma unroll
        for (int s = 0; s < 4; ++s) {
            Qh[s][0] = qh[(size_t)gid * 32 + 8 * s + tig];
            Qh[s][1] = qh[(size_t)(gid + 8) * 32 + 8 * s + tig];
            Qh[s][2] = qh[(size_t)gid * 32 + 8 * s + 4 + tig];
            Qh[s][3] = qh[(size_t)(gid + 8) * 32 + 8 * s + 4 + tig];
            Ql[s][0] = ql[(size_t)gid * 32 + 8 * s + tig];
            Ql[s][1] = ql[(size_t)(gid + 8) * 32 + 8 * s + tig];
            Ql[s][2] = ql[(size_t)gid * 32 + 8 * s + 4 + tig];
            Ql[s][3] = ql[(size_t)(gid + 8) * 32 + 8 * s + 4 + tig];
        }
    }

    float4 O[8];
    #pragma unroll
    for (int u = 0; u < 8; ++u) O[u] = make_float4(0.f, 0.f, 0.f, 0.f);
    float m0r = -1e30f, m1r = -1e30f, l0r = 0.f, l1r = 0.f;

    for (int kt = 0; kt < NSEQ / 128; ++kt) {
        __syncthreads();
        const uint4* Kh4 = (const uint4*)(g_kh2 + ((size_t)(b * NSEQ + kt * 128)) * 32);
        const uint4* Kl4 = (const uint4*)(g_kl2 + ((size_t)(b * NSEQ + kt * 128)) * 32);
        #pragma unroll
        for (int f = tid; f < 1024; f += 128) {
            int row = f >> 3, c = f & 7;
            *(uint4*)&sKh[row * KSTR + c * 4] = Kh4[row * 8 + c];
            *(uint4*)&sKl[row * KSTR + c * 4] = Kl4[row * 8 + c];
        }
        const uint4* Vh4 = (const uint4*)(g_vth2 + (size_t)b * HS * (NSEQ / 2));
        const uint4* Vl4 = (const uint4*)(g_vtl2 + (size_t)b * HS * (NSEQ / 2));
        #pragma unroll
        for (int f = tid; f < 1024; f += 128) {
            int h = f >> 4, c = f & 15;
            *(uint4*)&sVh[h * VSTR + c * 4] = Vh4[h * 512 + kt * 16 + c];
            *(uint4*)&sVl[h * VSTR + c * 4] = Vl4[h * 512 + kt * 16 + c];
        }
        __syncthreads();

        float4 S[16];
        #pragma unroll
        for (int t = 0; t < 16; ++t) S[t] = make_float4(0.f, 0.f, 0.f, 0.f);
        #pragma unroll
        for (int t = 0; t < 16; ++t) {
            int base = (8 * t + gid) * KSTR;
            #pragma unroll
            for (int s = 0; s < 4; ++s) {
                u32 bh0 = sKh[base + 8 * s + tig],     bh1 = sKh[base + 8 * s + 4 + tig];
                u32 bl0 = sKl[base + 8 * s + tig],     bl1 = sKl[base + 8 * s + 4 + tig];
                mma16816(S[t], Qh[s], bh0, bh1);
                mma16816(S[t], Qh[s], bl0, bl1);
                mma16816(S[t], Ql[s], bh0, bh1);
            }
        }

        float nm0 = m0r, nm1 = m1r;
        #pragma unroll
        for (int t = 0; t < 16; ++t) {
            nm0 = fmaxf(nm0, fmaxf(S[t].x, S[t].y));
            nm1 = fmaxf(nm1, fmaxf(S[t].z, S[t].w));
        }
        nm0 = fmaxf(nm0, __shfl_xor_sync(0xffffffffu, nm0, 1));
        nm0 = fmaxf(nm0, __shfl_xor_sync(0xffffffffu, nm0, 2));
        nm1 = fmaxf(nm1, __shfl_xor_sync(0xffffffffu, nm1, 1));
        nm1 = fmaxf(nm1, __shfl_xor_sync(0xffffffffu, nm1, 2));
        float al0 = __expf(m0r - nm0), al1 = __expf(m1r - nm1);
        m0r = nm0; m1r = nm1;
        float s0 = 0.f, s1 = 0.f;
        #pragma unroll
        for (int t = 0; t < 16; ++t) {
            S[t].x = __expf(S[t].x - nm0); S[t].y = __expf(S[t].y - nm0);
            S[t].z = __expf(S[t].z - nm1); S[t].w = __expf(S[t].w - nm1);
            s0 += S[t].x + S[t].y; s1 += S[t].z + S[t].w;
        }
        s0 += __shfl_xor_sync(0xffffffffu, s0, 1);
        s0 += __shfl_xor_sync(0xffffffffu, s0, 2);
        s1 += __shfl_xor_sync(0xffffffffu, s1, 1);
        s1 += __shfl_xor_sync(0xffffffffu, s1, 2);
        l0r = l0r * al0 + s0; l1r = l1r * al1 + s1;
        #pragma unroll
        for (int u = 0; u < 8; ++u) {
            O[u].x *= al0; O[u].y *= al0; O[u].z *= al1; O[u].w *= al1;
        }

        #pragma unroll
        for (int s = 0; s < 8; ++s) {
            u32 ph[4], pl[4];
            ph[0] = packbf(S[2 * s].x,     S[2 * s].y);
            ph[1] = packbf(S[2 * s].z,     S[2 * s].w);
            ph[2] = packbf(S[2 * s + 1].x, S[2 * s + 1].y);
            ph[3] = packbf(S[2 * s + 1].z, S[2 * s + 1].w);
            pl[0] = packbf(S[2 * s].x     - __uint_as_float(ph[0] << 16),
                           S[2 * s].y     - __uint_as_float(ph[0] & 0xFFFF0000u));
            pl[1] = packbf(S[2 * s].z     - __uint_as_float(ph[1] << 16),
                           S[2 * s].w     - __uint_as_float(ph[1] & 0xFFFF0000u));
            pl[2] = packbf(S[2 * s + 1].x - __uint_as_float(ph[2] << 16),
                           S[2 * s + 1].y - __uint_as_float(ph[2] & 0xFFFF0000u));
            pl[3] = packbf(S[2 * s + 1].z - __uint_as_float(ph[3] << 16),
                           S[2 * s + 1].w - __uint_as_float(ph[3] & 0xFFFF0000u));
            #pragma unroll
            for (int u = 0; u < 8; ++u) {
                int base = (8 * u + gid) * VSTR + 8 * s + tig;
                u32 bh0 = sVh[base], bh1 = sVh[base + 4];
                u32 bl0 = sVl[base], bl1 = sVl[base + 4];
                mma16816(O[u], ph, bh0, bh1);
                mma16816(O[u], ph, bl0, bl1);
                mma16816(O[u], pl, bh0, bh1);
            }
        }
    }

    float i0 = 1.f / l0r, i1 = 1.f / l1r;
    float* o0 = outp + ((size_t)(b * NSEQ + qt * 64 + w * 16 + gid)) * HS;
    float* o1 = o0 + 8 * HS;
    #pragma unroll
    for (int u = 0; u < 8; ++u) {
        *(float2*)(o0 + 8 * u + 2 * tig) = make_float2(O[u].x * i0, O[u].y * i0);
        *(float2*)(o1 + 8 * u + 2 * tig) = make_float2(O[u].z * i1, O[u].w * i1);
    }
}

// ---------------- Launch ----------------
extern "C" void kernel_launch(void* const* d_in, const int* in_sizes, int n_in,
                              void* d_out, int out_size)
{
    (void)in_sizes; (void)n_in; (void)out_size;
    const float* ix = (const float*)d_in[0];
    const float* Wk = (const float*)d_in[1];
    const float* Wq = (const float*)d_in[2];
    const float* Wv = (const float*)d_in[3];
    float* out = (float*)d_out;

    const int smem_bytes = (2 * 128 * KSTR + 2 * 64 * VSTR) * 4;  // 71680
    cudaFuncSetAttribute(flash_tc,
                         cudaFuncAttributeMaxDynamicSharedMemorySize, smem_bytes);

    dim3 pgrid(MROWS / 128, 3);                 // (128, 3)
    proj_tc<<<pgrid, 128>>>(ix, Wk, Wq, Wv);

    dim3 vgrid(NSEQ / 64, BATCH);
    vt_kernel<<<vgrid, 128>>>();

    flash_tc<<<BATCH * (NSEQ / 64), 128, smem_bytes>>>(out);  // 256 CTAs
}